// round 5
// baseline (speedup 1.0000x reference)
#include <cuda_runtime.h>

#define N_ROWS 32768
#define D_DIM  256
#define K_CODES 2048

#define BM 128   // rows per block
#define BN 128   // codes per tile
#define BK 16    // D chunk
#define TM 8
#define TN 8
#define XLD 132  // padded smem row stride (floats), keeps float4 alignment

#define NBLK (N_ROWS / BM)   // 256

__device__ float g_xnorm[N_ROWS];
__device__ float g_cnorm[K_CODES];
__device__ float g_partial[NBLK];

// ---------------------------------------------------------------------------
// Bit-exact replica of XLA:GPU row reduction for a 256-wide f32 row:
// 128 threads x vec2: lane partial s_t = fl(x[2t]^2 + x[2t+1]^2),
// intra-warp shfl_down tree (16,8,4,2,1), cross-warp (4 warps) combine via
// a second full-warp tree over {w0,w1,w2,w3,0,...} == fl(fl(w0+w2)+fl(w1+w3)).
// Executed here by ONE warp emulating XLA's 4 warps (g = warp index).
// ---------------------------------------------------------------------------
__device__ __forceinline__ float xla_row_sumsq(const float* __restrict__ row,
                                               int lane) {
    float s[4];
#pragma unroll
    for (int g = 0; g < 4; g++) {
        float x0 = row[64 * g + 2 * lane];
        float x1 = row[64 * g + 2 * lane + 1];
        s[g] = __fadd_rn(__fmul_rn(x0, x0), __fmul_rn(x1, x1));
    }
#pragma unroll
    for (int off = 16; off > 0; off >>= 1) {
#pragma unroll
        for (int g = 0; g < 4; g++)
            s[g] = __fadd_rn(s[g], __shfl_down_sync(0xffffffffu, s[g], off));
    }
    // cross-warp combine (XLA warp0 second tree): (w0+w2)+(w1+w3)
    return __fadd_rn(__fadd_rn(s[0], s[2]), __fadd_rn(s[1], s[3]));
}

// One warp per row; covers x rows then codebook rows.
__global__ void norms_kernel(const float* __restrict__ x,
                             const float* __restrict__ cb) {
    int warp = (blockIdx.x * blockDim.x + threadIdx.x) >> 5;
    int lane = threadIdx.x & 31;
    if (warp < N_ROWS) {
        float a = xla_row_sumsq(x + (size_t)warp * D_DIM, lane);
        if (lane == 0) g_xnorm[warp] = a;
    } else if (warp < N_ROWS + K_CODES) {
        int j = warp - N_ROWS;
        float b = xla_row_sumsq(cb + (size_t)j * D_DIM, lane);
        if (lane == 0) g_cnorm[j] = b;
    }
}

// ---------------------------------------------------------------------------
// Fused GEMM + quantized-argmin + gather + loss partial.
// Block = 128 rows x all 2048 codes (16 tiles of 128).
// Score replicates reference rounding exactly:
//   d = fl( fl(xnorm + cnorm) - fl(2 * dot) ), ties -> lowest index.
// ---------------------------------------------------------------------------
__global__ __launch_bounds__(256, 2)
void vq_main_kernel(const float* __restrict__ x, const float* __restrict__ cb,
                    float* __restrict__ out) {
    __shared__ float sX[BK * XLD];   // transposed X tile  [k][row]
    __shared__ float sC[BK * XLD];   // transposed C tile  [k][code]
    __shared__ float sCN[BN];
    __shared__ int   sWidx[BM];

    // aliases for the post-GEMM reductions (sX/sC no longer needed then)
    float* sred = sX;                // 16*128 floats <= 16*132
    int*   ired = (int*)sC;

    const int tid = threadIdx.x;
    const int tx  = tid & 15;
    const int ty  = tid >> 4;
    const int rowBase = blockIdx.x * BM;

    // per-thread row norms (bit-exact reference xnorm)
    float ar[TM];
#pragma unroll
    for (int r = 0; r < TM; r++) ar[r] = g_xnorm[rowBase + ty * TM + r];

    float bs[TM];
    int   bi[TM];
#pragma unroll
    for (int r = 0; r < TM; r++) { bs[r] = 3.4e38f; bi[r] = 0; }

    for (int t = 0; t < K_CODES / BN; t++) {
        __syncthreads();                       // prior tile's sCN reads done
        if (tid < BN) sCN[tid] = g_cnorm[t * BN + tid];

        float acc[TM][TN];
#pragma unroll
        for (int r = 0; r < TM; r++)
#pragma unroll
            for (int c = 0; c < TN; c++) acc[r][c] = 0.f;

        const float* cbase = cb + (size_t)(t * BN) * D_DIM;

        for (int dk = 0; dk < D_DIM; dk += BK) {
            __syncthreads();                   // prior compute done reading tiles
            // load + transpose: 512 float4 per tensor, 2 per thread
#pragma unroll
            for (int l = 0; l < 2; l++) {
                int i   = tid + l * 256;       // 0..511
                int row = i >> 2;              // 0..127
                int j   = (i & 3) << 2;        // 0,4,8,12
                float4 v = *(const float4*)(x + (size_t)(rowBase + row) * D_DIM + dk + j);
                sX[(j + 0) * XLD + row] = v.x;
                sX[(j + 1) * XLD + row] = v.y;
                sX[(j + 2) * XLD + row] = v.z;
                sX[(j + 3) * XLD + row] = v.w;
                float4 w = *(const float4*)(cbase + (size_t)row * D_DIM + dk + j);
                sC[(j + 0) * XLD + row] = w.x;
                sC[(j + 1) * XLD + row] = w.y;
                sC[(j + 2) * XLD + row] = w.z;
                sC[(j + 3) * XLD + row] = w.w;
            }
            __syncthreads();

#pragma unroll
            for (int k = 0; k < BK; k++) {
                const float4 a0 = *(const float4*)&sX[k * XLD + ty * TM];
                const float4 a1 = *(const float4*)&sX[k * XLD + ty * TM + 4];
                const float4 b0 = *(const float4*)&sC[k * XLD + tx * TN];
                const float4 b1 = *(const float4*)&sC[k * XLD + tx * TN + 4];
                const float xr[TM] = {a0.x, a0.y, a0.z, a0.w, a1.x, a1.y, a1.z, a1.w};
                const float cc[TN] = {b0.x, b0.y, b0.z, b0.w, b1.x, b1.y, b1.z, b1.w};
#pragma unroll
                for (int r = 0; r < TM; r++)
#pragma unroll
                    for (int c = 0; c < TN; c++)
                        acc[r][c] = fmaf(xr[r], cc[c], acc[r][c]);
            }
        }

        // quantized-argmin epilogue for this code tile. Exact reference
        // rounding chain; strict '<' with ascending code index keeps the
        // first (lowest-index) minimum, matching jnp.argmin.
#pragma unroll
        for (int r = 0; r < TM; r++) {
#pragma unroll
            for (int c = 0; c < TN; c++) {
                float T = __fadd_rn(ar[r], sCN[tx * TN + c]);
                float M = __fmul_rn(2.0f, acc[r][c]);
                float s = __fsub_rn(T, M);
                if (s < bs[r]) { bs[r] = s; bi[r] = t * BN + tx * TN + c; }
            }
        }
    }

    // cross-thread argmin reduction: 16 tx-threads share each row
    __syncthreads();
#pragma unroll
    for (int r = 0; r < TM; r++) {
        int srow = ty * TM + r;
        sred[tx * BM + srow] = bs[r];
        ired[tx * BM + srow] = bi[r];
    }
    __syncthreads();
    if (tid < BM) {
        float best = sred[tid];
        int   bidx = ired[tid];
#pragma unroll
        for (int p = 1; p < 16; p++) {
            float s = sred[p * BM + tid];
            int   id = ired[p * BM + tid];
            if (s < best || (s == best && id < bidx)) { best = s; bidx = id; }
        }
        sWidx[tid] = bidx;
    }
    __syncthreads();

    // gather winners, write x + (c - x) (reference's exact rounding), loss partial
    float lsum = 0.f;
    for (int i = tid; i < BM * (D_DIM / 4); i += 256) {
        int row = i >> 6;               // D_DIM/4 == 64
        int c4  = (i & 63) << 2;
        size_t goff = (size_t)(rowBase + row) * D_DIM + c4;
        float4 xv = *(const float4*)(x + goff);
        float4 cv = *(const float4*)(cb + (size_t)sWidx[row] * D_DIM + c4);
        float4 o;
        o.x = __fadd_rn(xv.x, __fsub_rn(cv.x, xv.x));
        o.y = __fadd_rn(xv.y, __fsub_rn(cv.y, xv.y));
        o.z = __fadd_rn(xv.z, __fsub_rn(cv.z, xv.z));
        o.w = __fadd_rn(xv.w, __fsub_rn(cv.w, xv.w));
        *(float4*)(out + goff) = o;
        float dx = __fsub_rn(xv.x, cv.x); lsum = fmaf(dx, dx, lsum);
        float dy = __fsub_rn(xv.y, cv.y); lsum = fmaf(dy, dy, lsum);
        float dz = __fsub_rn(xv.z, cv.z); lsum = fmaf(dz, dz, lsum);
        float dw = __fsub_rn(xv.w, cv.w); lsum = fmaf(dw, dw, lsum);
    }
    __syncthreads();
    sred[tid] = lsum;
    __syncthreads();
#pragma unroll
    for (int s = 128; s > 0; s >>= 1) {
        if (tid < s) sred[tid] += sred[tid + s];
        __syncthreads();
    }
    if (tid == 0) g_partial[blockIdx.x] = sred[0];
}

// ---------------------------------------------------------------------------
// Deterministic loss finalize. loss = 1.25 * mean((x-c)^2)
// (commit == embed bitwise in fp32, beta = 0.25).
// ---------------------------------------------------------------------------
__global__ void loss_kernel(float* __restrict__ out, int out_size) {
    __shared__ double sd[256];
    int tid = threadIdx.x;
    sd[tid] = (double)g_partial[tid];
    __syncthreads();
#pragma unroll
    for (int s = 128; s > 0; s >>= 1) {
        if (tid < s) sd[tid] += sd[tid + s];
        __syncthreads();
    }
    if (tid == 0) {
        double mean = sd[0] / (double)((size_t)N_ROWS * D_DIM);
        out[out_size - 1] = (float)(1.25 * mean);
    }
}

// ---------------------------------------------------------------------------
extern "C" void kernel_launch(void* const* d_in, const int* in_sizes, int n_in,
                              void* d_out, int out_size) {
    const float* x  = (const float*)d_in[0];   // [N, D]
    const float* cb = (const float*)d_in[1];   // [K, D]
    float* out = (float*)d_out;                // [N*D] quantized + [1] loss

    (void)in_sizes; (void)n_in;

    // (N_ROWS + K_CODES) rows, one warp each, 8 warps per block
    norms_kernel<<<(N_ROWS + K_CODES) / 8, 256>>>(x, cb);
    vq_main_kernel<<<NBLK, 256>>>(x, cb, out);
    loss_kernel<<<1, 256>>>(out, out_size);
}

// round 6
// speedup vs baseline: 1.0004x; 1.0004x over previous
#include <cuda_runtime.h>

#define N_ROWS 32768
#define D_DIM  256
#define K_CODES 2048

#define BM 128   // rows per block
#define BN 128   // codes per tile
#define BK 16    // D chunk
#define TM 8
#define TN 8
#define XLD 132  // padded smem row stride (floats), keeps float4 alignment

#define NBLK (N_ROWS / BM)   // 256

__device__ float g_xnorm[N_ROWS];
__device__ float g_cnorm[K_CODES];
__device__ float g_partial[NBLK];

// ---------------------------------------------------------------------------
// Bit-exact replica of XLA:GPU row reduction for a 256-wide f32 row:
// 128 threads x vec2: lane partial s_t = fl(x[2t]^2 + x[2t+1]^2),
// intra-warp shfl_down tree (16,8,4,2,1), cross-warp (4 warps) combine via
// a second full-warp tree over {w0,w1,w2,w3,0,...} == fl(fl(w0+w2)+fl(w1+w3)).
// Executed here by ONE warp emulating XLA's 4 warps (g = warp index).
// ---------------------------------------------------------------------------
__device__ __forceinline__ float xla_row_sumsq(const float* __restrict__ row,
                                               int lane) {
    float s[4];
#pragma unroll
    for (int g = 0; g < 4; g++) {
        float x0 = row[64 * g + 2 * lane];
        float x1 = row[64 * g + 2 * lane + 1];
        s[g] = __fadd_rn(__fmul_rn(x0, x0), __fmul_rn(x1, x1));
    }
#pragma unroll
    for (int off = 16; off > 0; off >>= 1) {
#pragma unroll
        for (int g = 0; g < 4; g++)
            s[g] = __fadd_rn(s[g], __shfl_down_sync(0xffffffffu, s[g], off));
    }
    // cross-warp combine (XLA warp0 second tree): (w0+w2)+(w1+w3)
    return __fadd_rn(__fadd_rn(s[0], s[2]), __fadd_rn(s[1], s[3]));
}

// One warp per row; covers x rows then codebook rows.
__global__ void norms_kernel(const float* __restrict__ x,
                             const float* __restrict__ cb) {
    int warp = (blockIdx.x * blockDim.x + threadIdx.x) >> 5;
    int lane = threadIdx.x & 31;
    if (warp < N_ROWS) {
        float a = xla_row_sumsq(x + (size_t)warp * D_DIM, lane);
        if (lane == 0) g_xnorm[warp] = a;
    } else if (warp < N_ROWS + K_CODES) {
        int j = warp - N_ROWS;
        float b = xla_row_sumsq(cb + (size_t)j * D_DIM, lane);
        if (lane == 0) g_cnorm[j] = b;
    }
}

// ---------------------------------------------------------------------------
// Fused GEMM + quantized-argmin + gather + loss partial.
// Block = 128 rows x all 2048 codes (16 tiles of 128).
// Score replicates reference rounding exactly:
//   d = fl( fl(xnorm + cnorm) - fl(2 * dot) ), ties -> lowest index.
// ---------------------------------------------------------------------------
__global__ __launch_bounds__(256, 2)
void vq_main_kernel(const float* __restrict__ x, const float* __restrict__ cb,
                    float* __restrict__ out) {
    __shared__ float sX[BK * XLD];   // transposed X tile  [k][row]
    __shared__ float sC[BK * XLD];   // transposed C tile  [k][code]
    __shared__ float sCN[BN];
    __shared__ int   sWidx[BM];

    // aliases for the post-GEMM reductions (sX/sC no longer needed then)
    float* sred = sX;                // 16*128 floats <= 16*132
    int*   ired = (int*)sC;

    const int tid = threadIdx.x;
    const int tx  = tid & 15;
    const int ty  = tid >> 4;
    const int rowBase = blockIdx.x * BM;

    // per-thread row norms (bit-exact reference xnorm)
    float ar[TM];
#pragma unroll
    for (int r = 0; r < TM; r++) ar[r] = g_xnorm[rowBase + ty * TM + r];

    float bs[TM];
    int   bi[TM];
#pragma unroll
    for (int r = 0; r < TM; r++) { bs[r] = 3.4e38f; bi[r] = 0; }

    for (int t = 0; t < K_CODES / BN; t++) {
        __syncthreads();                       // prior tile's sCN reads done
        if (tid < BN) sCN[tid] = g_cnorm[t * BN + tid];

        float acc[TM][TN];
#pragma unroll
        for (int r = 0; r < TM; r++)
#pragma unroll
            for (int c = 0; c < TN; c++) acc[r][c] = 0.f;

        const float* cbase = cb + (size_t)(t * BN) * D_DIM;

        for (int dk = 0; dk < D_DIM; dk += BK) {
            __syncthreads();                   // prior compute done reading tiles
            // load + transpose: 512 float4 per tensor, 2 per thread
#pragma unroll
            for (int l = 0; l < 2; l++) {
                int i   = tid + l * 256;       // 0..511
                int row = i >> 2;              // 0..127
                int j   = (i & 3) << 2;        // 0,4,8,12
                float4 v = *(const float4*)(x + (size_t)(rowBase + row) * D_DIM + dk + j);
                sX[(j + 0) * XLD + row] = v.x;
                sX[(j + 1) * XLD + row] = v.y;
                sX[(j + 2) * XLD + row] = v.z;
                sX[(j + 3) * XLD + row] = v.w;
                float4 w = *(const float4*)(cbase + (size_t)row * D_DIM + dk + j);
                sC[(j + 0) * XLD + row] = w.x;
                sC[(j + 1) * XLD + row] = w.y;
                sC[(j + 2) * XLD + row] = w.z;
                sC[(j + 3) * XLD + row] = w.w;
            }
            __syncthreads();

#pragma unroll
            for (int k = 0; k < BK; k++) {
                const float4 a0 = *(const float4*)&sX[k * XLD + ty * TM];
                const float4 a1 = *(const float4*)&sX[k * XLD + ty * TM + 4];
                const float4 b0 = *(const float4*)&sC[k * XLD + tx * TN];
                const float4 b1 = *(const float4*)&sC[k * XLD + tx * TN + 4];
                const float xr[TM] = {a0.x, a0.y, a0.z, a0.w, a1.x, a1.y, a1.z, a1.w};
                const float cc[TN] = {b0.x, b0.y, b0.z, b0.w, b1.x, b1.y, b1.z, b1.w};
#pragma unroll
                for (int r = 0; r < TM; r++)
#pragma unroll
                    for (int c = 0; c < TN; c++)
                        acc[r][c] = fmaf(xr[r], cc[c], acc[r][c]);
            }
        }

        // quantized-argmin epilogue for this code tile. Exact reference
        // rounding chain; strict '<' with ascending code index keeps the
        // first (lowest-index) minimum, matching jnp.argmin.
#pragma unroll
        for (int r = 0; r < TM; r++) {
#pragma unroll
            for (int c = 0; c < TN; c++) {
                float T = __fadd_rn(ar[r], sCN[tx * TN + c]);
                float M = __fmul_rn(2.0f, acc[r][c]);
                float s = __fsub_rn(T, M);
                if (s < bs[r]) { bs[r] = s; bi[r] = t * BN + tx * TN + c; }
            }
        }
    }

    // cross-thread argmin reduction: 16 tx-threads share each row
    __syncthreads();
#pragma unroll
    for (int r = 0; r < TM; r++) {
        int srow = ty * TM + r;
        sred[tx * BM + srow] = bs[r];
        ired[tx * BM + srow] = bi[r];
    }
    __syncthreads();
    if (tid < BM) {
        float best = sred[tid];
        int   bidx = ired[tid];
#pragma unroll
        for (int p = 1; p < 16; p++) {
            float s = sred[p * BM + tid];
            int   id = ired[p * BM + tid];
            if (s < best || (s == best && id < bidx)) { best = s; bidx = id; }
        }
        sWidx[tid] = bidx;
    }
    __syncthreads();

    // gather winners, write x + (c - x) (reference's exact rounding), loss partial
    float lsum = 0.f;
    for (int i = tid; i < BM * (D_DIM / 4); i += 256) {
        int row = i >> 6;               // D_DIM/4 == 64
        int c4  = (i & 63) << 2;
        size_t goff = (size_t)(rowBase + row) * D_DIM + c4;
        float4 xv = *(const float4*)(x + goff);
        float4 cv = *(const float4*)(cb + (size_t)sWidx[row] * D_DIM + c4);
        float4 o;
        o.x = __fadd_rn(xv.x, __fsub_rn(cv.x, xv.x));
        o.y = __fadd_rn(xv.y, __fsub_rn(cv.y, xv.y));
        o.z = __fadd_rn(xv.z, __fsub_rn(cv.z, xv.z));
        o.w = __fadd_rn(xv.w, __fsub_rn(cv.w, xv.w));
        *(float4*)(out + goff) = o;
        float dx = __fsub_rn(xv.x, cv.x); lsum = fmaf(dx, dx, lsum);
        float dy = __fsub_rn(xv.y, cv.y); lsum = fmaf(dy, dy, lsum);
        float dz = __fsub_rn(xv.z, cv.z); lsum = fmaf(dz, dz, lsum);
        float dw = __fsub_rn(xv.w, cv.w); lsum = fmaf(dw, dw, lsum);
    }
    __syncthreads();
    sred[tid] = lsum;
    __syncthreads();
#pragma unroll
    for (int s = 128; s > 0; s >>= 1) {
        if (tid < s) sred[tid] += sred[tid + s];
        __syncthreads();
    }
    if (tid == 0) g_partial[blockIdx.x] = sred[0];
}

// ---------------------------------------------------------------------------
// Deterministic loss finalize. loss = 1.25 * mean((x-c)^2)
// (commit == embed bitwise in fp32, beta = 0.25).
// ---------------------------------------------------------------------------
__global__ void loss_kernel(float* __restrict__ out, int out_size) {
    __shared__ double sd[256];
    int tid = threadIdx.x;
    sd[tid] = (double)g_partial[tid];
    __syncthreads();
#pragma unroll
    for (int s = 128; s > 0; s >>= 1) {
        if (tid < s) sd[tid] += sd[tid + s];
        __syncthreads();
    }
    if (tid == 0) {
        double mean = sd[0] / (double)((size_t)N_ROWS * D_DIM);
        out[out_size - 1] = (float)(1.25 * mean);
    }
}

// ---------------------------------------------------------------------------
extern "C" void kernel_launch(void* const* d_in, const int* in_sizes, int n_in,
                              void* d_out, int out_size) {
    const float* x  = (const float*)d_in[0];   // [N, D]
    const float* cb = (const float*)d_in[1];   // [K, D]
    float* out = (float*)d_out;                // [N*D] quantized + [1] loss

    (void)in_sizes; (void)n_in;

    // (N_ROWS + K_CODES) rows, one warp each, 8 warps per block
    norms_kernel<<<(N_ROWS + K_CODES) / 8, 256>>>(x, cb);
    vq_main_kernel<<<NBLK, 256>>>(x, cb, out);
    loss_kernel<<<1, 256>>>(out, out_size);
}